// round 1
// baseline (speedup 1.0000x reference)
#include <cuda_runtime.h>
#include <float.h>

// Problem constants (fixed by the reference)
#define T_LEN   2048
#define F_DIM   1024
#define NROWS   64          // total batch rows in features
#define BATCH   32
#define KSEL    20
#define P_DROP  0.1f

// Scratch: squared magnitudes (ordering key; sqrt/scale are monotone, skipped)
__device__ float g_mag2[NROWS * T_LEN];

// ---------------------------------------------------------------------------
// Kernel 1: one warp per (row, t) — sum of squares of 1024 floats.
// float4 loads: 8 per lane, fully coalesced. Pure HBM-streaming kernel.
// ---------------------------------------------------------------------------
__global__ void mag2_kernel(const float* __restrict__ feat) {
    int warp = (blockIdx.x * blockDim.x + threadIdx.x) >> 5;
    int lane = threadIdx.x & 31;
    if (warp >= NROWS * T_LEN) return;

    const float4* p = reinterpret_cast<const float4*>(feat + (size_t)warp * F_DIM);
    float s = 0.0f;
#pragma unroll
    for (int i = 0; i < 8; i++) {
        float4 v = p[lane + i * 32];
        s += v.x * v.x + v.y * v.y + v.z * v.z + v.w * v.w;
    }
#pragma unroll
    for (int o = 16; o; o >>= 1)
        s += __shfl_xor_sync(0xffffffffu, s, o);
    if (lane == 0) g_mag2[warp] = s;
}

// ---------------------------------------------------------------------------
// Kernel 2: one block per batch row (64 blocks, 256 threads).
//  - build keys: kept (mask > P) -> mag2 (>0), dropped -> -1
//  - 20 iterations of exact argmax (value desc, index asc) == jax top_k order
//  - score mean over selected indices
//  - gather 20 x 1024-float feature rows to output (float4 copies)
// ---------------------------------------------------------------------------
__global__ void topk_gather_kernel(const float* __restrict__ feat,
                                   const float* __restrict__ scores,
                                   const float* __restrict__ mask_abn,
                                   const float* __restrict__ mask_nor,
                                   float* __restrict__ out) {
    __shared__ float key[T_LEN];
    __shared__ float redv[256];
    __shared__ int   redi[256];
    __shared__ int   sel[KSEL];

    const int b    = blockIdx.x;          // 0..63 global feature row
    const int tid  = threadIdx.x;         // 0..255
    const bool abn = (b >= BATCH);        // rows [32,64) are "abnormal"
    const int  loc = abn ? b - BATCH : b;

    const float* mask = abn ? (mask_abn + (size_t)loc * T_LEN)
                            : (mask_nor + (size_t)loc * T_LEN);

    // Build selection keys. Dropped -> -1 (below any kept mag2 > 0); ties among
    // dropped resolve by ascending index, matching jax semantics for the
    // (practically impossible) <20-kept case.
    for (int t = tid; t < T_LEN; t += 256) {
        float m = mask[t];
        key[t] = (m > P_DROP) ? g_mag2[b * T_LEN + t] : -1.0f;
    }
    __syncthreads();

    float ssum = 0.0f;
    for (int k = 0; k < KSEL; k++) {
        // local argmax over strided slice (tie -> smaller index; t increases)
        float bv = -FLT_MAX;
        int   bi = T_LEN;
        for (int t = tid; t < T_LEN; t += 256) {
            float v = key[t];
            if (v > bv) { bv = v; bi = t; }
        }
        redv[tid] = bv;
        redi[tid] = bi;
        __syncthreads();
        // tree reduction with (value desc, index asc) comparator
        for (int s = 128; s; s >>= 1) {
            if (tid < s) {
                float ov = redv[tid + s];
                int   oi = redi[tid + s];
                if (ov > redv[tid] || (ov == redv[tid] && oi < redi[tid])) {
                    redv[tid] = ov;
                    redi[tid] = oi;
                }
            }
            __syncthreads();
        }
        const int idx = redi[0];
        if (tid == 0) {
            sel[k]   = idx;
            key[idx] = -FLT_MAX;                       // remove winner
            ssum    += scores[(size_t)b * T_LEN + idx];
        }
        __syncthreads();
    }

    // Score mean -> out[0:32) abnormal, out[32:64) normal
    if (tid == 0) {
        const int score_off = abn ? loc : (BATCH + loc);
        out[score_off] = ssum * (1.0f / (float)KSEL);
    }

    // Feature gather: abn block at offset 64, nor block after it.
    const size_t feat_base = abn ? (size_t)64
                                 : (size_t)64 + (size_t)BATCH * KSEL * F_DIM;
    const int F4 = F_DIM / 4;  // 256 float4 per feature row
    for (int i = tid; i < KSEL * F4; i += 256) {
        const int k = i / F4;
        const int c = i % F4;
        const int idx = sel[k];
        const float4 v = reinterpret_cast<const float4*>(
            feat + ((size_t)b * T_LEN + idx) * F_DIM)[c];
        reinterpret_cast<float4*>(
            out + feat_base + ((size_t)(loc * KSEL + k)) * F_DIM)[c] = v;
    }
}

// ---------------------------------------------------------------------------
extern "C" void kernel_launch(void* const* d_in, const int* in_sizes, int n_in,
                              void* d_out, int out_size) {
    const float* feat     = (const float*)d_in[0];  // (64, 2048, 1024) f32
    const float* scores   = (const float*)d_in[1];  // (64, 2048, 1)    f32
    const float* mask_abn = (const float*)d_in[2];  // (32, 2048)       f32
    const float* mask_nor = (const float*)d_in[3];  // (32, 2048)       f32
    float* out = (float*)d_out;

    // Kernel 1: 64*2048 warps, 8 warps/block -> 16384 blocks
    const int warps  = NROWS * T_LEN;
    const int blocks = (warps * 32 + 255) / 256;
    mag2_kernel<<<blocks, 256>>>(feat);

    // Kernel 2: one block per batch row
    topk_gather_kernel<<<NROWS, 256>>>(feat, scores, mask_abn, mask_nor, out);
}

// round 2
// speedup vs baseline: 1.1227x; 1.1227x over previous
#include <cuda_runtime.h>
#include <float.h>

// Problem constants (fixed by the reference)
#define T_LEN   2048
#define F_DIM   1024
#define NROWS   64          // total feature rows
#define BATCH   32
#define KSEL    20
#define P_DROP  0.1f

// Scratch (no device allocs allowed): squared magnitudes + selected indices
__device__ float g_mag2[NROWS * T_LEN];
__device__ int   g_sel[NROWS * KSEL];

// ---------------------------------------------------------------------------
// Kernel 1: one warp per (row, t) — sum of squares of 1024 floats.
// Pure HBM streaming: 512 MB read, ~6.6 TB/s (measured ceiling). Unchanged.
// ---------------------------------------------------------------------------
__global__ void mag2_kernel(const float* __restrict__ feat) {
    int warp = (blockIdx.x * blockDim.x + threadIdx.x) >> 5;
    int lane = threadIdx.x & 31;
    if (warp >= NROWS * T_LEN) return;

    const float4* p = reinterpret_cast<const float4*>(feat + (size_t)warp * F_DIM);
    float s = 0.0f;
#pragma unroll
    for (int i = 0; i < 8; i++) {
        float4 v = p[lane + i * 32];
        s += v.x * v.x + v.y * v.y + v.z * v.z + v.w * v.w;
    }
#pragma unroll
    for (int o = 16; o; o >>= 1)
        s += __shfl_xor_sync(0xffffffffu, s, o);
    if (lane == 0) g_mag2[warp] = s;
}

// ---------------------------------------------------------------------------
// Kernel 2: selection — ONE WARP per feature row, zero block barriers.
// Each lane owns a 64-element blocked slice of the 2048 keys (in smem).
// 20 rounds of: shfl argmax (5 steps, tie -> smaller index) + winner-lane
// rescan of its 64 elements. Then one parallel score load + warp sum.
// Launch: 64 blocks x 32 threads.
// ---------------------------------------------------------------------------
__global__ void select_kernel(const float* __restrict__ scores,
                              const float* __restrict__ mask_abn,
                              const float* __restrict__ mask_nor,
                              float* __restrict__ out) {
    __shared__ float key[T_LEN];

    const int b    = blockIdx.x;      // 0..63
    const int lane = threadIdx.x;     // 0..31
    const bool abn = (b >= BATCH);
    const int  loc = abn ? b - BATCH : b;

    const float* mask = abn ? (mask_abn + (size_t)loc * T_LEN)
                            : (mask_nor + (size_t)loc * T_LEN);

    // Build keys: kept -> mag2 (>0), dropped -> -1 (monotone transform of the
    // reference's mag*drop: sqrt and 1/(1-P) scale preserve order; dropped
    // values are 0 in the reference, strictly below any kept value, and tie
    // among themselves -> index asc, which our comparator reproduces).
    for (int t = lane; t < T_LEN; t += 32) {
        key[t] = (mask[t] > P_DROP) ? g_mag2[b * T_LEN + t] : -1.0f;
    }
    __syncwarp();

    // Each lane's blocked slice: [lane*64, lane*64+64)
    const int base = lane * 64;
    float bv = -FLT_MAX;
    int   bi = T_LEN;
#pragma unroll 8
    for (int j = 0; j < 64; j++) {
        float v = key[base + j];
        if (v > bv) { bv = v; bi = base + j; }   // strict > keeps smallest idx
    }

    int sel_local[KSEL];

#pragma unroll 1
    for (int k = 0; k < KSEL; k++) {
        // warp argmax with (value desc, index asc) tie-break
        float wv = bv;
        int   wi = bi;
#pragma unroll
        for (int o = 16; o; o >>= 1) {
            float ov = __shfl_xor_sync(0xffffffffu, wv, o);
            int   oi = __shfl_xor_sync(0xffffffffu, wi, o);
            if (ov > wv || (ov == wv && oi < wi)) { wv = ov; wi = oi; }
        }
        sel_local[k] = wi;

        // winning lane removes the element and rescans its slice
        if ((wi >> 6) == lane) {
            key[wi] = -FLT_MAX;
            bv = -FLT_MAX;
            bi = T_LEN;
#pragma unroll 8
            for (int j = 0; j < 64; j++) {
                float v = key[base + j];
                if (v > bv) { bv = v; bi = base + j; }
            }
        }
        __syncwarp();
    }

    // Persist selected indices for the gather kernel (lane k writes sel[k])
    if (lane < KSEL)
        g_sel[b * KSEL + lane] = sel_local[lane];

    // Score mean: load all 20 selected scores in parallel, warp-reduce.
    float s = (lane < KSEL) ? scores[(size_t)b * T_LEN + sel_local[lane]] : 0.0f;
#pragma unroll
    for (int o = 16; o; o >>= 1)
        s += __shfl_xor_sync(0xffffffffu, s, o);
    if (lane == 0) {
        const int score_off = abn ? loc : (BATCH + loc);
        out[score_off] = s * (1.0f / (float)KSEL);
    }
}

// ---------------------------------------------------------------------------
// Kernel 3: gather — one block per selected feature row (64*20 = 1280 blocks),
// 256 threads x 1 float4 = 1024 floats. Fully parallel, ~10.5 MB traffic.
// ---------------------------------------------------------------------------
__global__ void gather_kernel(const float* __restrict__ feat,
                              float* __restrict__ out) {
    const int blk = blockIdx.x;        // 0..1279
    const int b   = blk / KSEL;        // feature row 0..63
    const int k   = blk % KSEL;
    const bool abn = (b >= BATCH);
    const int  loc = abn ? b - BATCH : b;

    const int idx = g_sel[b * KSEL + k];

    // Output layout: [score_abn(32) | score_nor(32) | abn_feat | nor_feat]
    const size_t feat_base = abn ? (size_t)64
                                 : (size_t)64 + (size_t)BATCH * KSEL * F_DIM;

    const float4 v = reinterpret_cast<const float4*>(
        feat + ((size_t)b * T_LEN + idx) * F_DIM)[threadIdx.x];
    reinterpret_cast<float4*>(
        out + feat_base + (size_t)(loc * KSEL + k) * F_DIM)[threadIdx.x] = v;
}

// ---------------------------------------------------------------------------
extern "C" void kernel_launch(void* const* d_in, const int* in_sizes, int n_in,
                              void* d_out, int out_size) {
    const float* feat     = (const float*)d_in[0];  // (64, 2048, 1024) f32
    const float* scores   = (const float*)d_in[1];  // (64, 2048, 1)    f32
    const float* mask_abn = (const float*)d_in[2];  // (32, 2048)       f32
    const float* mask_nor = (const float*)d_in[3];  // (32, 2048)       f32
    float* out = (float*)d_out;

    const int warps  = NROWS * T_LEN;
    const int blocks = (warps * 32 + 255) / 256;
    mag2_kernel<<<blocks, 256>>>(feat);

    select_kernel<<<NROWS, 32>>>(scores, mask_abn, mask_nor, out);

    gather_kernel<<<NROWS * KSEL, 256>>>(feat, out);
}

// round 3
// speedup vs baseline: 1.3479x; 1.2006x over previous
#include <cuda_runtime.h>
#include <float.h>

// Problem constants (fixed by the reference)
#define T_LEN   2048
#define F_DIM   1024
#define NROWS   64          // total feature rows
#define BATCH   32
#define KSEL    20
#define P_DROP  0.1f

// Scratch (no device allocs allowed): masked selection keys + selected indices
__device__ float g_key[NROWS * T_LEN];
__device__ int   g_sel[NROWS * KSEL];

// ---------------------------------------------------------------------------
// Kernel 1: one warp per (row, t) — sum of squares of 1024 floats, with the
// dropout mask fused in: key = (mask > P) ? sum_sq : -1.
// (sqrt and the 1/(1-P) scale are monotone -> ordering identical to the
// reference's mag*drop; dropped entries are 0 there, strictly below any kept
// value, and -1 here preserves that relation.)
// Pure HBM streaming: 512 MB read @ ~6.9 TB/s — this is the roofline.
// ---------------------------------------------------------------------------
__global__ void key_kernel(const float* __restrict__ feat,
                           const float* __restrict__ mask_abn,
                           const float* __restrict__ mask_nor) {
    int warp = (blockIdx.x * blockDim.x + threadIdx.x) >> 5;
    int lane = threadIdx.x & 31;
    if (warp >= NROWS * T_LEN) return;

    // Preload mask early on lane 0 to overlap with the feature stream.
    float m = 0.0f;
    if (lane == 0) {
        const int b = warp >> 11;          // feature row 0..63
        const int t = warp & (T_LEN - 1);
        const float* mask = (b >= BATCH)
            ? (mask_abn + (size_t)(b - BATCH) * T_LEN)
            : (mask_nor + (size_t)b * T_LEN);
        m = mask[t];
    }

    const float4* p = reinterpret_cast<const float4*>(feat + (size_t)warp * F_DIM);
    float s = 0.0f;
#pragma unroll
    for (int i = 0; i < 8; i++) {
        float4 v = p[lane + i * 32];
        s += v.x * v.x + v.y * v.y + v.z * v.z + v.w * v.w;
    }
#pragma unroll
    for (int o = 16; o; o >>= 1)
        s += __shfl_xor_sync(0xffffffffu, s, o);

    if (lane == 0)
        g_key[warp] = (m > P_DROP) ? s : -1.0f;
}

// ---------------------------------------------------------------------------
// Kernel 2: selection — ONE WARP per feature row, fully cooperative.
// Keys live in smem; each lane caches the argmax of its 64-element slice.
// Per round: 5-shfl warp argmax (value desc, index asc), remove winner, then
// ALL 32 lanes cooperatively rescan the winner's 64-element slice (2 elems
// per lane + 5-shfl argmax) and hand the result to the owner lane.
// ---------------------------------------------------------------------------
__global__ void select_kernel(const float* __restrict__ scores,
                              float* __restrict__ out) {
    __shared__ float key[T_LEN];

    const int b    = blockIdx.x;      // 0..63
    const int lane = threadIdx.x;     // 0..31
    const bool abn = (b >= BATCH);
    const int  loc = abn ? b - BATCH : b;

    // Load this row's keys (vectorized: 16 float4 per lane)
    {
        const float4* src = reinterpret_cast<const float4*>(g_key + (size_t)b * T_LEN);
        float4*       dst = reinterpret_cast<float4*>(key);
#pragma unroll
        for (int i = 0; i < 16; i++)
            dst[lane + i * 32] = src[lane + i * 32];
    }
    __syncwarp();

    // Initial per-lane argmax over its contiguous 64-element slice.
    const int base = lane * 64;
    float bv = -FLT_MAX;
    int   bi = T_LEN;
#pragma unroll 8
    for (int j = 0; j < 64; j++) {
        float v = key[base + j];
        if (v > bv) { bv = v; bi = base + j; }   // strict > keeps smallest idx
    }

    int sel_local[KSEL];

#pragma unroll 1
    for (int k = 0; k < KSEL; k++) {
        // Warp argmax with (value desc, index asc) tie-break.
        float wv = bv;
        int   wi = bi;
#pragma unroll
        for (int o = 16; o; o >>= 1) {
            float ov = __shfl_xor_sync(0xffffffffu, wv, o);
            int   oi = __shfl_xor_sync(0xffffffffu, wi, o);
            if (ov > wv || (ov == wv && oi < wi)) { wv = ov; wi = oi; }
        }
        sel_local[k] = wi;

        const int owner = wi >> 6;
        if (lane == owner) key[wi] = -FLT_MAX;     // remove winner
        __syncwarp();

        // Cooperative rescan of the owner's slice: 2 elements per lane.
        const int rb = owner << 6;
        float rv;
        int   ri;
        {
            float v0 = key[rb + lane];
            float v1 = key[rb + lane + 32];
            if (v0 >= v1) { rv = v0; ri = rb + lane; }        // >= keeps lower idx
            else          { rv = v1; ri = rb + lane + 32; }
        }
#pragma unroll
        for (int o = 16; o; o >>= 1) {
            float ov = __shfl_xor_sync(0xffffffffu, rv, o);
            int   oi = __shfl_xor_sync(0xffffffffu, rv == ov ? __shfl_xor_sync(0xffffffffu, ri, o) : __shfl_xor_sync(0xffffffffu, ri, o), o) ; // placeholder avoided below
            (void)oi;
            break; // replaced by explicit loop below
        }
        // explicit (value desc, index asc) warp argmax
#pragma unroll
        for (int o = 16; o; o >>= 1) {
            float ov = __shfl_xor_sync(0xffffffffu, rv, o);
            int   oi = __shfl_xor_sync(0xffffffffu, ri, o);
            if (ov > rv || (ov == rv && oi < ri)) { rv = ov; ri = oi; }
        }
        if (lane == owner) { bv = rv; bi = ri; }
        __syncwarp();
    }

    // Persist selected indices for the gather kernel.
    if (lane < KSEL)
        g_sel[b * KSEL + lane] = sel_local[lane];

    // Score mean: load all 20 selected scores in parallel, warp-reduce.
    float s = (lane < KSEL) ? scores[(size_t)b * T_LEN + sel_local[lane]] : 0.0f;
#pragma unroll
    for (int o = 16; o; o >>= 1)
        s += __shfl_xor_sync(0xffffffffu, s, o);
    if (lane == 0) {
        const int score_off = abn ? loc : (BATCH + loc);
        out[score_off] = s * (1.0f / (float)KSEL);
    }
}

// ---------------------------------------------------------------------------
// Kernel 3: gather — one block per selected feature row (64*20 = 1280 blocks),
// 256 threads x 1 float4 = 1024 floats. Fully parallel, ~10.5 MB traffic.
// ---------------------------------------------------------------------------
__global__ void gather_kernel(const float* __restrict__ feat,
                              float* __restrict__ out) {
    const int blk = blockIdx.x;        // 0..1279
    const int b   = blk / KSEL;        // feature row 0..63
    const int k   = blk % KSEL;
    const bool abn = (b >= BATCH);
    const int  loc = abn ? b - BATCH : b;

    const int idx = g_sel[b * KSEL + k];

    // Output layout: [score_abn(32) | score_nor(32) | abn_feat | nor_feat]
    const size_t feat_base = abn ? (size_t)64
                                 : (size_t)64 + (size_t)BATCH * KSEL * F_DIM;

    const float4 v = reinterpret_cast<const float4*>(
        feat + ((size_t)b * T_LEN + idx) * F_DIM)[threadIdx.x];
    reinterpret_cast<float4*>(
        out + feat_base + (size_t)(loc * KSEL + k) * F_DIM)[threadIdx.x] = v;
}

// ---------------------------------------------------------------------------
extern "C" void kernel_launch(void* const* d_in, const int* in_sizes, int n_in,
                              void* d_out, int out_size) {
    const float* feat     = (const float*)d_in[0];  // (64, 2048, 1024) f32
    const float* scores   = (const float*)d_in[1];  // (64, 2048, 1)    f32
    const float* mask_abn = (const float*)d_in[2];  // (32, 2048)       f32
    const float* mask_nor = (const float*)d_in[3];  // (32, 2048)       f32
    float* out = (float*)d_out;

    const int warps  = NROWS * T_LEN;
    const int blocks = (warps * 32 + 255) / 256;
    key_kernel<<<blocks, 256>>>(feat, mask_abn, mask_nor);

    select_kernel<<<NROWS, 32>>>(scores, out);

    gather_kernel<<<NROWS * KSEL, 256>>>(feat, out);
}

// round 4
// speedup vs baseline: 1.3637x; 1.0117x over previous
#include <cuda_runtime.h>
#include <float.h>

// Problem constants (fixed by the reference)
#define T_LEN   2048
#define F_DIM   1024
#define NROWS   64          // total feature rows
#define BATCH   32
#define KSEL    20
#define P_DROP  0.1f

// Scratch (no device allocs allowed): masked selection keys
__device__ float g_key[NROWS * T_LEN];

// ---------------------------------------------------------------------------
// Kernel 1: one warp per (row, t) — sum of squares of 1024 floats, with the
// dropout mask fused in: key = (mask > P) ? sum_sq : -1.
// (sqrt and the 1/(1-P) scale are monotone -> ordering identical to the
// reference's mag*drop; dropped entries are 0 there, strictly below any kept
// value, and -1 here preserves that relation.)
// Pure HBM streaming: 512 MB read @ ~7.0 TB/s — this is the roofline.
// ---------------------------------------------------------------------------
__global__ void key_kernel(const float* __restrict__ feat,
                           const float* __restrict__ mask_abn,
                           const float* __restrict__ mask_nor) {
    int warp = (blockIdx.x * blockDim.x + threadIdx.x) >> 5;
    int lane = threadIdx.x & 31;

    // Preload mask early on lane 0 to overlap with the feature stream.
    float m = 0.0f;
    if (lane == 0) {
        const int b = warp >> 11;          // feature row 0..63
        const int t = warp & (T_LEN - 1);
        const float* mask = (b >= BATCH)
            ? (mask_abn + (size_t)(b - BATCH) * T_LEN)
            : (mask_nor + (size_t)b * T_LEN);
        m = mask[t];
    }

    const float4* p = reinterpret_cast<const float4*>(feat + (size_t)warp * F_DIM);
    float s = 0.0f;
#pragma unroll
    for (int i = 0; i < 8; i++) {
        float4 v = p[lane + i * 32];
        s += v.x * v.x + v.y * v.y + v.z * v.z + v.w * v.w;
    }
#pragma unroll
    for (int o = 16; o; o >>= 1)
        s += __shfl_xor_sync(0xffffffffu, s, o);

    if (lane == 0)
        g_key[warp] = (m > P_DROP) ? s : -1.0f;
}

// ---------------------------------------------------------------------------
// Kernel 2 (fused select + gather): one block (256 threads) per feature row.
//  - all threads cooperatively stage the row's 2048 keys into smem
//  - warp 0 runs 20 rounds of exact warp argmax (value desc, index asc),
//    with cooperative rescan of the winner's 64-element slice; computes the
//    score mean in parallel at the end
//  - all 8 warps then gather the 20 selected 1024-float feature rows
// ---------------------------------------------------------------------------
__global__ void select_gather_kernel(const float* __restrict__ feat,
                                     const float* __restrict__ scores,
                                     float* __restrict__ out) {
    __shared__ float key[T_LEN];
    __shared__ int   sel[KSEL];

    const int b    = blockIdx.x;      // 0..63
    const int tid  = threadIdx.x;     // 0..255
    const int lane = tid & 31;
    const int warp = tid >> 5;
    const bool abn = (b >= BATCH);
    const int  loc = abn ? b - BATCH : b;

    // Stage keys: 512 float4 across 256 threads (2 each) — full-block MLP.
    {
        const float4* src = reinterpret_cast<const float4*>(g_key + (size_t)b * T_LEN);
        float4*       dst = reinterpret_cast<float4*>(key);
        dst[tid]       = src[tid];
        dst[tid + 256] = src[tid + 256];
    }
    __syncthreads();

    if (warp == 0) {
        // Initial per-lane argmax over its contiguous 64-element slice.
        const int base = lane * 64;
        float bv = -FLT_MAX;
        int   bi = T_LEN;
#pragma unroll 8
        for (int j = 0; j < 64; j++) {
            float v = key[base + j];
            if (v > bv) { bv = v; bi = base + j; }   // strict > keeps smallest idx
        }

        int sel_local[KSEL];

#pragma unroll 1
        for (int k = 0; k < KSEL; k++) {
            // Warp argmax with (value desc, index asc) tie-break.
            float wv = bv;
            int   wi = bi;
#pragma unroll
            for (int o = 16; o; o >>= 1) {
                float ov = __shfl_xor_sync(0xffffffffu, wv, o);
                int   oi = __shfl_xor_sync(0xffffffffu, wi, o);
                if (ov > wv || (ov == wv && oi < wi)) { wv = ov; wi = oi; }
            }
            sel_local[k] = wi;

            const int owner = wi >> 6;
            if (lane == owner) key[wi] = -FLT_MAX;     // remove winner
            __syncwarp();

            // Cooperative rescan of the owner's slice: 2 elements per lane.
            const int rb = owner << 6;
            float rv;
            int   ri;
            {
                float v0 = key[rb + lane];
                float v1 = key[rb + lane + 32];
                if (v0 >= v1) { rv = v0; ri = rb + lane; }    // >= keeps lower idx
                else          { rv = v1; ri = rb + lane + 32; }
            }
#pragma unroll
            for (int o = 16; o; o >>= 1) {
                float ov = __shfl_xor_sync(0xffffffffu, rv, o);
                int   oi = __shfl_xor_sync(0xffffffffu, ri, o);
                if (ov > rv || (ov == rv && oi < ri)) { rv = ov; ri = oi; }
            }
            if (lane == owner) { bv = rv; bi = ri; }
            __syncwarp();
        }

        // Publish indices to the block.
        if (lane < KSEL) sel[lane] = sel_local[lane];

        // Score mean: load all 20 selected scores in parallel, warp-reduce.
        float s = (lane < KSEL) ? scores[(size_t)b * T_LEN + sel_local[lane]] : 0.0f;
#pragma unroll
        for (int o = 16; o; o >>= 1)
            s += __shfl_xor_sync(0xffffffffu, s, o);
        if (lane == 0) {
            const int score_off = abn ? loc : (BATCH + loc);
            out[score_off] = s * (1.0f / (float)KSEL);
        }
    }
    __syncthreads();

    // Gather: 20 rows x 256 float4 = 5120 float4 across 256 threads (20 each).
    // Output layout: [score_abn(32) | score_nor(32) | abn_feat | nor_feat]
    const size_t feat_base = abn ? (size_t)64
                                 : (size_t)64 + (size_t)BATCH * KSEL * F_DIM;
    const float4* fsrc = reinterpret_cast<const float4*>(feat);
    float4*       fdst = reinterpret_cast<float4*>(out + feat_base);

#pragma unroll
    for (int k = 0; k < KSEL; k++) {
        const int idx = sel[k];
        fdst[(size_t)(loc * KSEL + k) * 256 + tid] =
            fsrc[((size_t)b * T_LEN + idx) * 256 + tid];
    }
}

// ---------------------------------------------------------------------------
extern "C" void kernel_launch(void* const* d_in, const int* in_sizes, int n_in,
                              void* d_out, int out_size) {
    const float* feat     = (const float*)d_in[0];  // (64, 2048, 1024) f32
    const float* scores   = (const float*)d_in[1];  // (64, 2048, 1)    f32
    const float* mask_abn = (const float*)d_in[2];  // (32, 2048)       f32
    const float* mask_nor = (const float*)d_in[3];  // (32, 2048)       f32
    float* out = (float*)d_out;

    const int warps  = NROWS * T_LEN;
    const int blocks = (warps * 32) / 256;          // exact: 16384
    key_kernel<<<blocks, 256>>>(feat, mask_abn, mask_nor);

    select_gather_kernel<<<NROWS, 256>>>(feat, scores, out);
}